// round 1
// baseline (speedup 1.0000x reference)
#include <cuda_runtime.h>
#include <cuda_bf16.h>
#include <cstdint>

// ---------------- problem constants ----------------
#define B_SZ 4
#define LSEQ 2048
#define DMODEL 1024
#define DINNER 2048
#define DSTATE 16
#define DCONV 4
#define MROWS (B_SZ * LSEQ)          // 8192

// ---------------- scratch (static __device__, no allocations) ----------------
__device__ float g_XN[MROWS * DMODEL];          // layernorm out        33.5 MB
__device__ float g_XZ[(size_t)MROWS * 2 * DINNER]; // in-proj out       134 MB
__device__ float g_XC[(size_t)MROWS * DINNER];  // conv+silu out        67 MB
__device__ float g_DELTA[(size_t)MROWS * DINNER]; // softplus(delta)    67 MB
__device__ float g_BM[MROWS * DSTATE];
__device__ float g_CM[MROWS * DSTATE];
__device__ float g_YW[(size_t)MROWS * DINNER];  // y * silu(z)          67 MB

// ---------------- LayerNorm: one block per row ----------------
__global__ __launch_bounds__(256) void ln_kernel(const float* __restrict__ x,
                                                 const float* __restrict__ w,
                                                 const float* __restrict__ b) {
    int row = blockIdx.x;
    int tid = threadIdx.x;
    const float4 v = ((const float4*)(x + (size_t)row * DMODEL))[tid];
    float s  = v.x + v.y + v.z + v.w;
    float sq = v.x*v.x + v.y*v.y + v.z*v.z + v.w*v.w;
    #pragma unroll
    for (int o = 16; o > 0; o >>= 1) {
        s  += __shfl_xor_sync(0xffffffffu, s, o);
        sq += __shfl_xor_sync(0xffffffffu, sq, o);
    }
    __shared__ float ss[8], sqs[8];
    if ((tid & 31) == 0) { ss[tid >> 5] = s; sqs[tid >> 5] = sq; }
    __syncthreads();
    float tot = 0.f, totq = 0.f;
    #pragma unroll
    for (int p = 0; p < 8; p++) { tot += ss[p]; totq += sqs[p]; }
    float mean = tot * (1.f / DMODEL);
    float var  = totq * (1.f / DMODEL) - mean * mean;
    float r = rsqrtf(var + 1e-5f);
    const float4 w4 = ((const float4*)w)[tid];
    const float4 b4 = ((const float4*)b)[tid];
    float4 o;
    o.x = (v.x - mean) * r * w4.x + b4.x;
    o.y = (v.y - mean) * r * w4.y + b4.y;
    o.z = (v.z - mean) * r * w4.z + b4.z;
    o.w = (v.w - mean) * r * w4.w + b4.w;
    ((float4*)(g_XN + (size_t)row * DMODEL))[tid] = o;
}

// ---------------- tiled SGEMM: C[M,N] = A[M,K] @ B[K,N] (+epilogue) ----------------
// MODE 0: plain   MODE 1: softplus(acc + bias[col])   MODE 2: acc + res[row*N+col]
template <int MODE>
__global__ __launch_bounds__(256) void sgemm128(const float* __restrict__ A,
                                                const float* __restrict__ B,
                                                float* __restrict__ C,
                                                int M, int N, int K,
                                                const float* __restrict__ bias,
                                                const float* __restrict__ res) {
    __shared__ float As[8][128];
    __shared__ float Bs[8][128];
    int tid = threadIdx.x;
    int bx = blockIdx.x, by = blockIdx.y;
    int tx = tid & 15, ty = tid >> 4;

    const float* Ab = A + (size_t)by * 128 * K;
    const float* Bb = B + bx * 128;

    int aRow = tid >> 1, aCol = (tid & 1) * 4;
    int bRow = tid >> 5, bCol = (tid & 31) * 4;

    float acc[8][8];
    #pragma unroll
    for (int i = 0; i < 8; i++)
        #pragma unroll
        for (int j = 0; j < 8; j++) acc[i][j] = 0.f;

    for (int k0 = 0; k0 < K; k0 += 8) {
        float4 a4 = *(const float4*)(Ab + (size_t)aRow * K + k0 + aCol);
        As[aCol + 0][aRow] = a4.x;
        As[aCol + 1][aRow] = a4.y;
        As[aCol + 2][aRow] = a4.z;
        As[aCol + 3][aRow] = a4.w;
        float4 b4 = *(const float4*)(Bb + (size_t)(k0 + bRow) * N + bCol);
        *(float4*)(&Bs[bRow][bCol]) = b4;
        __syncthreads();
        #pragma unroll
        for (int kk = 0; kk < 8; kk++) {
            float ar[8], br[8];
            *(float4*)(ar)     = *(const float4*)(&As[kk][ty * 8]);
            *(float4*)(ar + 4) = *(const float4*)(&As[kk][ty * 8 + 4]);
            *(float4*)(br)     = *(const float4*)(&Bs[kk][tx * 8]);
            *(float4*)(br + 4) = *(const float4*)(&Bs[kk][tx * 8 + 4]);
            #pragma unroll
            for (int i = 0; i < 8; i++)
                #pragma unroll
                for (int j = 0; j < 8; j++)
                    acc[i][j] = fmaf(ar[i], br[j], acc[i][j]);
        }
        __syncthreads();
    }

    #pragma unroll
    for (int i = 0; i < 8; i++) {
        int row = by * 128 + ty * 8 + i;
        #pragma unroll
        for (int j0 = 0; j0 < 8; j0 += 4) {
            int col0 = bx * 128 + tx * 8 + j0;
            float4 o;
            float v[4];
            #pragma unroll
            for (int j = 0; j < 4; j++) {
                float a = acc[i][j0 + j];
                if (MODE == 1) {
                    a += bias[col0 + j];
                    // stable softplus
                    a = fmaxf(a, 0.f) + log1pf(expf(-fabsf(a)));
                } else if (MODE == 2) {
                    a += res[(size_t)row * N + col0 + j];
                }
                v[j] = a;
            }
            o.x = v[0]; o.y = v[1]; o.z = v[2]; o.w = v[3];
            *(float4*)(C + (size_t)row * N + col0) = o;
        }
    }
}

// ---------------- depthwise causal conv (K=4) + SiLU ----------------
__global__ __launch_bounds__(256) void conv_kernel(const float* __restrict__ cw,
                                                   const float* __restrict__ cb) {
    int idx = blockIdx.x * 256 + threadIdx.x;      // over B*L*DINNER
    int d = idx & (DINNER - 1);
    int l = (idx >> 11) & (LSEQ - 1);
    int b = idx >> 22;
    float acc = cb[d];
    #pragma unroll
    for (int k = 0; k < DCONV; k++) {
        int t = l - (DCONV - 1) + k;
        if (t >= 0)
            acc = fmaf(cw[d * DCONV + k],
                       g_XZ[((size_t)(b * LSEQ + t)) * (2 * DINNER) + d], acc);
    }
    float s = acc / (1.f + __expf(-acc));          // silu
    g_XC[(size_t)idx] = s;
}

// ---------------- B/C projections: one block per (b,l) row ----------------
__global__ __launch_bounds__(256) void bc_kernel(const float* __restrict__ Wb,
                                                 const float* __restrict__ Wc) {
    __shared__ float rowsh[DINNER];
    __shared__ float red[8][32];
    int row = blockIdx.x;
    int tid = threadIdx.x;
    const float4* xr = (const float4*)(g_XC + (size_t)row * DINNER);
    #pragma unroll
    for (int i = 0; i < 2; i++)
        *(float4*)(&rowsh[(tid + i * 256) * 4]) = xr[tid + i * 256];
    __syncthreads();
    int out = tid & 31;
    int part = tid >> 5;
    const float* W = (out < 16) ? Wb : Wc;
    int col = out & 15;
    float s = 0.f;
    int k0 = part * 256;
    for (int k = k0; k < k0 + 256; k++)
        s = fmaf(rowsh[k], W[k * DSTATE + col], s);
    red[part][out] = s;
    __syncthreads();
    if (tid < 32) {
        float t = 0.f;
        #pragma unroll
        for (int p = 0; p < 8; p++) t += red[p][tid];
        if (tid < 16) g_BM[row * DSTATE + tid] = t;
        else          g_CM[row * DSTATE + (tid - 16)] = t;
    }
}

// ---------------- selective scan + gate: thread per (b,d) ----------------
#define SCAN_BLK 64
#define SCAN_CH 64
__global__ __launch_bounds__(SCAN_BLK) void scan_kernel(const float* __restrict__ A_log,
                                                        const float* __restrict__ Dp_) {
    int b = blockIdx.y;
    int d = blockIdx.x * SCAN_BLK + threadIdx.x;
    int tid = threadIdx.x;

    float A[DSTATE], h[DSTATE];
    #pragma unroll
    for (int n = 0; n < DSTATE; n++) {
        A[n] = -__expf(A_log[d * DSTATE + n]);
        h[n] = 0.f;
    }
    float Dp = Dp_[d];

    __shared__ float Bsh[SCAN_CH][DSTATE];
    __shared__ float Csh[SCAN_CH][DSTATE];

    for (int t0 = 0; t0 < LSEQ; t0 += SCAN_CH) {
        int base = (b * LSEQ + t0) * DSTATE;
        for (int i = tid; i < SCAN_CH * DSTATE; i += SCAN_BLK) {
            Bsh[i >> 4][i & 15] = g_BM[base + i];
            Csh[i >> 4][i & 15] = g_CM[base + i];
        }
        __syncthreads();
        for (int tt = 0; tt < SCAN_CH; tt++) {
            int t = t0 + tt;
            size_t rb = (size_t)(b * LSEQ + t) * DINNER + d;
            float dt = g_DELTA[rb];
            float xt = g_XC[rb];
            float dx = dt * xt;
            float y = 0.f;
            #pragma unroll
            for (int n = 0; n < DSTATE; n++) {
                float ab = __expf(dt * A[n]);
                h[n] = fmaf(ab, h[n], dx * Bsh[tt][n]);
                y = fmaf(h[n], Csh[tt][n], y);
            }
            y = fmaf(Dp, xt, y);
            float z = g_XZ[(size_t)(b * LSEQ + t) * (2 * DINNER) + DINNER + d];
            float sz = z / (1.f + __expf(-z));
            g_YW[rb] = y * sz;
        }
        __syncthreads();
    }
}

// ---------------- launch ----------------
extern "C" void kernel_launch(void* const* d_in, const int* in_sizes, int n_in,
                              void* d_out, int out_size) {
    const float* x       = (const float*)d_in[0];
    const float* norm_w  = (const float*)d_in[1];
    const float* norm_b  = (const float*)d_in[2];
    const float* W_in    = (const float*)d_in[3];
    const float* conv_w  = (const float*)d_in[4];
    const float* conv_b  = (const float*)d_in[5];
    const float* A_log   = (const float*)d_in[6];
    const float* W_b     = (const float*)d_in[7];
    const float* W_c     = (const float*)d_in[8];
    const float* W_delta = (const float*)d_in[9];
    const float* b_delta = (const float*)d_in[10];
    const float* D_param = (const float*)d_in[11];
    const float* W_out   = (const float*)d_in[12];
    float* out = (float*)d_out;

    void *pXN, *pXZ, *pXC, *pDELTA, *pYW;
    cudaGetSymbolAddress(&pXN, g_XN);
    cudaGetSymbolAddress(&pXZ, g_XZ);
    cudaGetSymbolAddress(&pXC, g_XC);
    cudaGetSymbolAddress(&pDELTA, g_DELTA);
    cudaGetSymbolAddress(&pYW, g_YW);

    // 1) layernorm
    ln_kernel<<<MROWS, 256>>>(x, norm_w, norm_b);

    // 2) xz = xn @ W_in  [8192,1024]@[1024,4096]
    sgemm128<0><<<dim3(2 * DINNER / 128, MROWS / 128), 256>>>(
        (const float*)pXN, W_in, (float*)pXZ, MROWS, 2 * DINNER, DMODEL, nullptr, nullptr);

    // 3) depthwise causal conv + silu
    conv_kernel<<<(B_SZ * LSEQ * DINNER) / 256, 256>>>(conv_w, conv_b);

    // 4) delta = softplus(xc @ W_delta + b_delta)  [8192,2048]@[2048,2048]
    sgemm128<1><<<dim3(DINNER / 128, MROWS / 128), 256>>>(
        (const float*)pXC, W_delta, (float*)pDELTA, MROWS, DINNER, DINNER, b_delta, nullptr);

    // 5) B/C projections
    bc_kernel<<<MROWS, 256>>>(W_b, W_c);

    // 6) selective scan + D skip + silu(z) gate
    scan_kernel<<<dim3(DINNER / SCAN_BLK, B_SZ), SCAN_BLK>>>(A_log, D_param);

    // 7) out = yw @ W_out + residual  [8192,2048]@[2048,1024]
    sgemm128<2><<<dim3(DMODEL / 128, MROWS / 128), 256>>>(
        (const float*)pYW, W_out, out, MROWS, DMODEL, DINNER, nullptr, x);
}

// round 4
// speedup vs baseline: 1.6300x; 1.6300x over previous
#include <cuda_runtime.h>
#include <cuda_bf16.h>
#include <cstdint>

// ---------------- problem constants ----------------
#define B_SZ 4
#define LSEQ 2048
#define DMODEL 1024
#define DINNER 2048
#define DSTATE 16
#define DCONV 4
#define MROWS (B_SZ * LSEQ)          // 8192

// ---------------- scratch (static __device__, no allocations) ----------------
__device__ float g_XZ[(size_t)MROWS * 2 * DINNER];   // in-proj out fp32
__device__ float g_XC[(size_t)MROWS * DINNER];       // conv+silu out fp32 (scan/bc)
__device__ float g_DELTA[(size_t)MROWS * DINNER];    // softplus delta fp32
__device__ float g_BM[MROWS * DSTATE];
__device__ float g_CM[MROWS * DSTATE];

__device__ __align__(16) __nv_bfloat16 g_XNh[(size_t)MROWS * DMODEL];
__device__ __align__(16) __nv_bfloat16 g_XNl[(size_t)MROWS * DMODEL];
__device__ __align__(16) __nv_bfloat16 g_XCh[(size_t)MROWS * DINNER];
__device__ __align__(16) __nv_bfloat16 g_XCl[(size_t)MROWS * DINNER];
__device__ __align__(16) __nv_bfloat16 g_YWh[(size_t)MROWS * DINNER];
__device__ __align__(16) __nv_bfloat16 g_YWl[(size_t)MROWS * DINNER];
// transposed split weights: [N][K] bf16
__device__ __align__(16) __nv_bfloat16 g_Wih[(size_t)2 * DINNER * DMODEL];
__device__ __align__(16) __nv_bfloat16 g_Wil[(size_t)2 * DINNER * DMODEL];
__device__ __align__(16) __nv_bfloat16 g_Wdh[(size_t)DINNER * DINNER];
__device__ __align__(16) __nv_bfloat16 g_Wdl[(size_t)DINNER * DINNER];
__device__ __align__(16) __nv_bfloat16 g_Woh[(size_t)DMODEL * DINNER];
__device__ __align__(16) __nv_bfloat16 g_Wol[(size_t)DMODEL * DINNER];

// ---------------- PTX helpers (sm_80-level only; compute_103-safe) ----------------
__device__ __forceinline__ uint32_t smem_u32(const void* p) {
    uint32_t a;
    asm("{ .reg .u64 t; cvta.to.shared.u64 t, %1; cvt.u32.u64 %0, t; }" : "=r"(a) : "l"(p));
    return a;
}
__device__ __forceinline__ void cp16(uint32_t saddr, const void* g) {
    asm volatile("cp.async.cg.shared.global [%0], [%1], 16;" :: "r"(saddr), "l"(g));
}
#define CP_COMMIT() asm volatile("cp.async.commit_group;" ::: "memory")
#define CP_WAIT(n)  asm volatile("cp.async.wait_group %0;" :: "n"(n) : "memory")

__device__ __forceinline__ void ldsm4(uint32_t (&r)[4], uint32_t addr) {
    asm volatile("ldmatrix.sync.aligned.m8n8.x4.shared.b16 {%0,%1,%2,%3}, [%4];"
                 : "=r"(r[0]), "=r"(r[1]), "=r"(r[2]), "=r"(r[3]) : "r"(addr));
}
__device__ __forceinline__ void mma16816(float (&d)[4], const uint32_t (&a)[4],
                                         const uint32_t* b) {
    asm volatile(
        "mma.sync.aligned.m16n8k16.row.col.f32.bf16.bf16.f32 "
        "{%0,%1,%2,%3}, {%4,%5,%6,%7}, {%8,%9}, {%0,%1,%2,%3};"
        : "+f"(d[0]), "+f"(d[1]), "+f"(d[2]), "+f"(d[3])
        : "r"(a[0]), "r"(a[1]), "r"(a[2]), "r"(a[3]), "r"(b[0]), "r"(b[1]));
}
#define SW128(o) ((o) ^ (((o) >> 3) & 0x70))

// ---------------- LayerNorm -> split bf16 ----------------
__global__ __launch_bounds__(256) void ln_kernel(const float* __restrict__ x,
                                                 const float* __restrict__ w,
                                                 const float* __restrict__ b) {
    int row = blockIdx.x;
    int tid = threadIdx.x;
    const float4 v = ((const float4*)(x + (size_t)row * DMODEL))[tid];
    float s  = v.x + v.y + v.z + v.w;
    float sq = v.x*v.x + v.y*v.y + v.z*v.z + v.w*v.w;
    #pragma unroll
    for (int o = 16; o > 0; o >>= 1) {
        s  += __shfl_xor_sync(0xffffffffu, s, o);
        sq += __shfl_xor_sync(0xffffffffu, sq, o);
    }
    __shared__ float ss[8], sqs[8];
    if ((tid & 31) == 0) { ss[tid >> 5] = s; sqs[tid >> 5] = sq; }
    __syncthreads();
    float tot = 0.f, totq = 0.f;
    #pragma unroll
    for (int p = 0; p < 8; p++) { tot += ss[p]; totq += sqs[p]; }
    float mean = tot * (1.f / DMODEL);
    float var  = totq * (1.f / DMODEL) - mean * mean;
    float r = rsqrtf(var + 1e-5f);
    const float4 w4 = ((const float4*)w)[tid];
    const float4 b4 = ((const float4*)b)[tid];
    float o[4];
    o[0] = (v.x - mean) * r * w4.x + b4.x;
    o[1] = (v.y - mean) * r * w4.y + b4.y;
    o[2] = (v.z - mean) * r * w4.z + b4.z;
    o[3] = (v.w - mean) * r * w4.w + b4.w;
    __nv_bfloat16 h[4], l[4];
    #pragma unroll
    for (int i = 0; i < 4; i++) {
        h[i] = __float2bfloat16(o[i]);
        l[i] = __float2bfloat16(o[i] - __bfloat162float(h[i]));
    }
    size_t base = (size_t)row * DMODEL + tid * 4;
    *(__nv_bfloat162*)(g_XNh + base)     = __halves2bfloat162(h[0], h[1]);
    *(__nv_bfloat162*)(g_XNh + base + 2) = __halves2bfloat162(h[2], h[3]);
    *(__nv_bfloat162*)(g_XNl + base)     = __halves2bfloat162(l[0], l[1]);
    *(__nv_bfloat162*)(g_XNl + base + 2) = __halves2bfloat162(l[2], l[3]);
}

// ---------------- weight transpose + split: W[K][N] -> Th/Tl[N][K] ----------------
__global__ __launch_bounds__(256) void wtrans_kernel(const float* __restrict__ W,
                                                     __nv_bfloat16* __restrict__ Th,
                                                     __nv_bfloat16* __restrict__ Tl,
                                                     int K, int N) {
    __shared__ float t[32][33];
    int n0 = blockIdx.x * 32, k0 = blockIdx.y * 32;
    int tx = threadIdx.x & 31, ty = threadIdx.x >> 5;   // 32 x 8
    #pragma unroll
    for (int i = 0; i < 4; i++)
        t[ty + 8 * i][tx] = W[(size_t)(k0 + ty + 8 * i) * N + n0 + tx];
    __syncthreads();
    #pragma unroll
    for (int i = 0; i < 4; i++) {
        int n = ty + 8 * i, kk = tx;
        float v = t[kk][n];
        __nv_bfloat16 h = __float2bfloat16(v);
        Th[(size_t)(n0 + n) * K + k0 + kk] = h;
        Tl[(size_t)(n0 + n) * K + k0 + kk] = __float2bfloat16(v - __bfloat162float(h));
    }
}

// ---------------- split-bf16 mma.sync GEMM: C[M,N] = A @ B^T ----------------
// A: Ah/Al [M][K] bf16 ; B: Bh/Bl [N][K] bf16 (pre-transposed weights)
// MODE 0: plain  MODE 1: softplus(acc + bias[col])  MODE 2: acc + res[row*ldc+col]
// CTA tile 128x128, K-chunk 64; 2-stage cp.async pipeline; SW128 smem swizzle.
#define TILE_B   16384                // one 128x64 bf16 tile
#define STAGE_B  (4 * TILE_B)         // Ah,Al,Bh,Bl
#define GEMM_SMEM (2 * STAGE_B)       // 131072

template <int MODE>
__global__ void __launch_bounds__(256)
tgemm_kernel(const __nv_bfloat16* __restrict__ Ah, const __nv_bfloat16* __restrict__ Al,
             const __nv_bfloat16* __restrict__ Bh, const __nv_bfloat16* __restrict__ Bl,
             float* __restrict__ C, int K, int ldc,
             const float* __restrict__ bias, const float* __restrict__ res) {
    extern __shared__ char smem[];
    uint32_t sb = smem_u32(smem);
    int tid = threadIdx.x, lane = tid & 31, wid = tid >> 5;
    int warp_m = wid & 1;          // 2 x 64 rows
    int warp_n = wid >> 1;         // 4 x 32 cols
    int m0 = blockIdx.y * 128, n0 = blockIdx.x * 128;

    float acc[4][4][4];
    #pragma unroll
    for (int i = 0; i < 4; i++)
        #pragma unroll
        for (int j = 0; j < 4; j++)
            #pragma unroll
            for (int q = 0; q < 4; q++) acc[i][j][q] = 0.f;

    // ---- load mapping: thread -> (row = tid/2, half = tid&1), 4 x 16B per tile
    int lrow = tid >> 1, lhalf = tid & 1;
    const char* gAh = (const char*)(Ah + (size_t)(m0 + lrow) * K) + lhalf * 64;
    const char* gAl = (const char*)(Al + (size_t)(m0 + lrow) * K) + lhalf * 64;
    const char* gBh = (const char*)(Bh + (size_t)(n0 + lrow) * K) + lhalf * 64;
    const char* gBl = (const char*)(Bl + (size_t)(n0 + lrow) * K) + lhalf * 64;
    uint32_t swo[4];
    #pragma unroll
    for (int i = 0; i < 4; i++)
        swo[i] = SW128((uint32_t)(lrow * 128 + lhalf * 64 + i * 16));

    int nc = K >> 6;

    // ---- prefetch chunk 0 into stage 0
    {
        uint32_t base = sb;
        #pragma unroll
        for (int i = 0; i < 4; i++) {
            cp16(base + swo[i],              gAh + i * 16);
            cp16(base + TILE_B + swo[i],     gAl + i * 16);
            cp16(base + 2 * TILE_B + swo[i], gBh + i * 16);
            cp16(base + 3 * TILE_B + swo[i], gBl + i * 16);
        }
        CP_COMMIT();
    }

    for (int c = 0; c < nc; c++) {
        if (c + 1 < nc) {
            uint32_t base = sb + ((c + 1) & 1) * STAGE_B;
            size_t kb = (size_t)(c + 1) * 128;
            #pragma unroll
            for (int i = 0; i < 4; i++) {
                cp16(base + swo[i],              gAh + kb + i * 16);
                cp16(base + TILE_B + swo[i],     gAl + kb + i * 16);
                cp16(base + 2 * TILE_B + swo[i], gBh + kb + i * 16);
                cp16(base + 3 * TILE_B + swo[i], gBl + kb + i * 16);
            }
            CP_COMMIT();
            CP_WAIT(1);
        } else {
            CP_WAIT(0);
        }
        __syncthreads();

        uint32_t cbase = sb + (c & 1) * STAGE_B;
        #pragma unroll
        for (int ks = 0; ks < 4; ks++) {
            uint32_t afh[4][4], afl[4][4];
            uint32_t bfh[2][4], bfl[2][4];
            #pragma unroll
            for (int mi = 0; mi < 4; mi++) {
                uint32_t off = SW128((uint32_t)((warp_m * 64 + mi * 16 + (lane & 15)) * 128
                                                + ks * 32 + (lane >> 4) * 16));
                ldsm4(afh[mi], cbase + off);
                ldsm4(afl[mi], cbase + TILE_B + off);
            }
            #pragma unroll
            for (int p = 0; p < 2; p++) {
                uint32_t off = SW128((uint32_t)((warp_n * 32 + p * 16 + ((lane >> 4) & 1) * 8
                                                + (lane & 7)) * 128
                                                + ks * 32 + ((lane >> 3) & 1) * 16));
                ldsm4(bfh[p], cbase + 2 * TILE_B + off);
                ldsm4(bfl[p], cbase + 3 * TILE_B + off);
            }
            #pragma unroll
            for (int mi = 0; mi < 4; mi++) {
                #pragma unroll
                for (int ni = 0; ni < 4; ni++) {
                    const uint32_t* bh = &bfh[ni >> 1][(ni & 1) * 2];
                    const uint32_t* bl = &bfl[ni >> 1][(ni & 1) * 2];
                    mma16816(acc[mi][ni], afh[mi], bh);
                    mma16816(acc[mi][ni], afh[mi], bl);
                    mma16816(acc[mi][ni], afl[mi], bh);
                }
            }
        }
        __syncthreads();
    }

    // ---- epilogue straight from register accumulators
    #pragma unroll
    for (int mi = 0; mi < 4; mi++) {
        int r0 = m0 + warp_m * 64 + mi * 16 + (lane >> 2);
        #pragma unroll
        for (int ni = 0; ni < 4; ni++) {
            int col = n0 + warp_n * 32 + ni * 8 + (lane & 3) * 2;
            #pragma unroll
            for (int half = 0; half < 2; half++) {
                int row = r0 + half * 8;
                float a0 = acc[mi][ni][half * 2 + 0];
                float a1 = acc[mi][ni][half * 2 + 1];
                if (MODE == 1) {
                    a0 += bias[col];
                    a1 += bias[col + 1];
                    a0 = fmaxf(a0, 0.f) + log1pf(expf(-fabsf(a0)));
                    a1 = fmaxf(a1, 0.f) + log1pf(expf(-fabsf(a1)));
                } else if (MODE == 2) {
                    const float2 rr = *(const float2*)(res + (size_t)row * ldc + col);
                    a0 += rr.x; a1 += rr.y;
                }
                float2 o; o.x = a0; o.y = a1;
                *(float2*)(C + (size_t)row * ldc + col) = o;
            }
        }
    }
}

// ---------------- depthwise causal conv (K=4) + SiLU -> fp32 + split bf16 ----------------
__global__ __launch_bounds__(256) void conv_kernel(const float* __restrict__ cw,
                                                   const float* __restrict__ cb) {
    int idx = blockIdx.x * 256 + threadIdx.x;
    int d = idx & (DINNER - 1);
    int l = (idx >> 11) & (LSEQ - 1);
    int b = idx >> 22;
    float acc = cb[d];
    #pragma unroll
    for (int k = 0; k < DCONV; k++) {
        int t = l - (DCONV - 1) + k;
        if (t >= 0)
            acc = fmaf(cw[d * DCONV + k],
                       g_XZ[((size_t)(b * LSEQ + t)) * (2 * DINNER) + d], acc);
    }
    float s = acc / (1.f + __expf(-acc));
    g_XC[(size_t)idx] = s;
    __nv_bfloat16 h = __float2bfloat16(s);
    g_XCh[(size_t)idx] = h;
    g_XCl[(size_t)idx] = __float2bfloat16(s - __bfloat162float(h));
}

// ---------------- B/C projections: 32 rows per block, W staged via smem ----------------
__global__ __launch_bounds__(256) void bc_kernel(const float* __restrict__ Wb,
                                                 const float* __restrict__ Wc) {
    __shared__ float Xs[32][132];
    __shared__ float Ws[128][32];
    int tid = threadIdx.x;
    int out = tid & 31, rg = tid >> 5;         // 8 rowgroups x 4 rows
    int rb0 = blockIdx.x * 32;
    float acc[4] = {0.f, 0.f, 0.f, 0.f};

    for (int k0 = 0; k0 < DINNER; k0 += 128) {
        #pragma unroll
        for (int i = 0; i < 4; i++) {
            int lin = tid + i * 256;
            int rr = lin >> 5, c4 = lin & 31;
            *(float4*)(&Xs[rr][c4 * 4]) =
                *(const float4*)(g_XC + (size_t)(rb0 + rr) * DINNER + k0 + c4 * 4);
        }
        #pragma unroll
        for (int i = 0; i < 2; i++) {
            int lin = tid + i * 256;
            int kk = lin >> 2, q = lin & 3;
            *(float4*)(&Ws[kk][q * 4]) = *(const float4*)(Wb + (size_t)(k0 + kk) * DSTATE + q * 4);
        }
        #pragma unroll
        for (int i = 0; i < 2; i++) {
            int lin = tid + i * 256;
            int kk = lin >> 2, q = lin & 3;
            *(float4*)(&Ws[kk][16 + q * 4]) = *(const float4*)(Wc + (size_t)(k0 + kk) * DSTATE + q * 4);
        }
        __syncthreads();
        for (int k = 0; k < 128; k++) {
            float w = Ws[k][out];
            #pragma unroll
            for (int i = 0; i < 4; i++)
                acc[i] = fmaf(Xs[rg * 4 + i][k], w, acc[i]);
        }
        __syncthreads();
    }
    #pragma unroll
    for (int i = 0; i < 4; i++) {
        int row = rb0 + rg * 4 + i;
        if (out < DSTATE) g_BM[row * DSTATE + out] = acc[i];
        else              g_CM[row * DSTATE + (out - DSTATE)] = acc[i];
    }
}

// ---------------- selective scan + gate -> split bf16 ----------------
#define SCAN_BLK 64
#define SCAN_CH 64
__global__ __launch_bounds__(SCAN_BLK) void scan_kernel(const float* __restrict__ A_log,
                                                        const float* __restrict__ Dp_) {
    int b = blockIdx.y;
    int d = blockIdx.x * SCAN_BLK + threadIdx.x;
    int tid = threadIdx.x;

    float A[DSTATE], h[DSTATE];
    #pragma unroll
    for (int n = 0; n < DSTATE; n++) {
        A[n] = -__expf(A_log[d * DSTATE + n]);
        h[n] = 0.f;
    }
    float Dp = Dp_[d];

    __shared__ float Bsh[SCAN_CH][DSTATE];
    __shared__ float Csh[SCAN_CH][DSTATE];

    for (int t0 = 0; t0 < LSEQ; t0 += SCAN_CH) {
        int base = (b * LSEQ + t0) * DSTATE;
        for (int i = tid; i < SCAN_CH * DSTATE; i += SCAN_BLK) {
            Bsh[i >> 4][i & 15] = g_BM[base + i];
            Csh[i >> 4][i & 15] = g_CM[base + i];
        }
        __syncthreads();
        for (int tt = 0; tt < SCAN_CH; tt++) {
            int t = t0 + tt;
            size_t rb = (size_t)(b * LSEQ + t) * DINNER + d;
            float dt = g_DELTA[rb];
            float xt = g_XC[rb];
            float dx = dt * xt;
            float y = 0.f;
            #pragma unroll
            for (int n = 0; n < DSTATE; n++) {
                float ab = __expf(dt * A[n]);
                h[n] = fmaf(ab, h[n], dx * Bsh[tt][n]);
                y = fmaf(h[n], Csh[tt][n], y);
            }
            y = fmaf(Dp, xt, y);
            float z = g_XZ[(size_t)(b * LSEQ + t) * (2 * DINNER) + DINNER + d];
            float sz = z / (1.f + __expf(-z));
            float v = y * sz;
            __nv_bfloat16 hv = __float2bfloat16(v);
            g_YWh[rb] = hv;
            g_YWl[rb] = __float2bfloat16(v - __bfloat162float(hv));
        }
        __syncthreads();
    }
}

// ---------------- launch ----------------
extern "C" void kernel_launch(void* const* d_in, const int* in_sizes, int n_in,
                              void* d_out, int out_size) {
    const float* x       = (const float*)d_in[0];
    const float* norm_w  = (const float*)d_in[1];
    const float* norm_b  = (const float*)d_in[2];
    const float* W_in    = (const float*)d_in[3];
    const float* conv_w  = (const float*)d_in[4];
    const float* conv_b  = (const float*)d_in[5];
    const float* A_log   = (const float*)d_in[6];
    const float* W_b     = (const float*)d_in[7];
    const float* W_c     = (const float*)d_in[8];
    const float* W_delta = (const float*)d_in[9];
    const float* b_delta = (const float*)d_in[10];
    const float* D_param = (const float*)d_in[11];
    const float* W_out   = (const float*)d_in[12];
    float* out = (float*)d_out;

    void *pXZ, *pDELTA;
    void *pXNh, *pXNl, *pXCh, *pXCl, *pYWh, *pYWl;
    void *pWih, *pWil, *pWdh, *pWdl, *pWoh, *pWol;
    cudaGetSymbolAddress(&pXZ, g_XZ);
    cudaGetSymbolAddress(&pDELTA, g_DELTA);
    cudaGetSymbolAddress(&pXNh, g_XNh);  cudaGetSymbolAddress(&pXNl, g_XNl);
    cudaGetSymbolAddress(&pXCh, g_XCh);  cudaGetSymbolAddress(&pXCl, g_XCl);
    cudaGetSymbolAddress(&pYWh, g_YWh);  cudaGetSymbolAddress(&pYWl, g_YWl);
    cudaGetSymbolAddress(&pWih, g_Wih);  cudaGetSymbolAddress(&pWil, g_Wil);
    cudaGetSymbolAddress(&pWdh, g_Wdh);  cudaGetSymbolAddress(&pWdl, g_Wdl);
    cudaGetSymbolAddress(&pWoh, g_Woh);  cudaGetSymbolAddress(&pWol, g_Wol);

    cudaFuncSetAttribute(tgemm_kernel<0>, cudaFuncAttributeMaxDynamicSharedMemorySize, GEMM_SMEM);
    cudaFuncSetAttribute(tgemm_kernel<1>, cudaFuncAttributeMaxDynamicSharedMemorySize, GEMM_SMEM);
    cudaFuncSetAttribute(tgemm_kernel<2>, cudaFuncAttributeMaxDynamicSharedMemorySize, GEMM_SMEM);

    // weight transpose + bf16 split
    wtrans_kernel<<<dim3(2 * DINNER / 32, DMODEL / 32), 256>>>(
        W_in, (__nv_bfloat16*)pWih, (__nv_bfloat16*)pWil, DMODEL, 2 * DINNER);
    wtrans_kernel<<<dim3(DINNER / 32, DINNER / 32), 256>>>(
        W_delta, (__nv_bfloat16*)pWdh, (__nv_bfloat16*)pWdl, DINNER, DINNER);
    wtrans_kernel<<<dim3(DMODEL / 32, DINNER / 32), 256>>>(
        W_out, (__nv_bfloat16*)pWoh, (__nv_bfloat16*)pWol, DINNER, DMODEL);

    // 1) layernorm -> XN hi/lo
    ln_kernel<<<MROWS, 256>>>(x, norm_w, norm_b);

    // 2) xz = xn @ W_in  [8192,1024] x [1024,4096]
    tgemm_kernel<0><<<dim3(2 * DINNER / 128, MROWS / 128), 256, GEMM_SMEM>>>(
        (const __nv_bfloat16*)pXNh, (const __nv_bfloat16*)pXNl,
        (const __nv_bfloat16*)pWih, (const __nv_bfloat16*)pWil,
        (float*)pXZ, DMODEL, 2 * DINNER, nullptr, nullptr);

    // 3) depthwise causal conv + silu -> XC fp32 + hi/lo
    conv_kernel<<<(B_SZ * LSEQ * DINNER) / 256, 256>>>(conv_w, conv_b);

    // 4) delta = softplus(xc @ W_delta + b_delta)  [8192,2048] x [2048,2048]
    tgemm_kernel<1><<<dim3(DINNER / 128, MROWS / 128), 256, GEMM_SMEM>>>(
        (const __nv_bfloat16*)pXCh, (const __nv_bfloat16*)pXCl,
        (const __nv_bfloat16*)pWdh, (const __nv_bfloat16*)pWdl,
        (float*)pDELTA, DINNER, DINNER, b_delta, nullptr);

    // 5) B/C projections
    bc_kernel<<<MROWS / 32, 256>>>(W_b, W_c);

    // 6) selective scan + D skip + silu(z) gate -> YW hi/lo
    scan_kernel<<<dim3(DINNER / SCAN_BLK, B_SZ), SCAN_BLK>>>(A_log, D_param);

    // 7) out = yw @ W_out + residual  [8192,2048] x [2048,1024]
    tgemm_kernel<2><<<dim3(DMODEL / 128, MROWS / 128), 256, GEMM_SMEM>>>(
        (const __nv_bfloat16*)pYWh, (const __nv_bfloat16*)pYWl,
        (const __nv_bfloat16*)pWoh, (const __nv_bfloat16*)pWol,
        out, DINNER, DMODEL, nullptr, x);
}

// round 5
// speedup vs baseline: 2.2476x; 1.3789x over previous
#include <cuda_runtime.h>
#include <cuda_fp16.h>
#include <cstdint>

// ---------------- problem constants ----------------
#define B_SZ 4
#define LSEQ 2048
#define DMODEL 1024
#define DINNER 2048
#define DSTATE 16
#define DCONV 4
#define MROWS (B_SZ * LSEQ)          // 8192

// ---------------- scratch (static __device__, no allocations) ----------------
__device__ float g_XZ[(size_t)MROWS * 2 * DINNER];   // in-proj out fp32
__device__ float g_XC[(size_t)MROWS * DINNER];       // conv+silu out fp32 (scan/bc)
__device__ float g_DELTA[(size_t)MROWS * DINNER];    // softplus delta fp32
__device__ float g_BM[MROWS * DSTATE];
__device__ float g_CM[MROWS * DSTATE];

__device__ __align__(16) __half g_XNh[(size_t)MROWS * DMODEL];
__device__ __align__(16) __half g_XCh[(size_t)MROWS * DINNER];
__device__ __align__(16) __half g_YWh[(size_t)MROWS * DINNER];
// transposed fp16 weights: [N][K]
__device__ __align__(16) __half g_Wih[(size_t)2 * DINNER * DMODEL];
__device__ __align__(16) __half g_Wdh[(size_t)DINNER * DINNER];
__device__ __align__(16) __half g_Woh[(size_t)DMODEL * DINNER];

// ---------------- PTX helpers (sm_80-level; compute_103-safe) ----------------
__device__ __forceinline__ uint32_t smem_u32(const void* p) {
    uint32_t a;
    asm("{ .reg .u64 t; cvta.to.shared.u64 t, %1; cvt.u32.u64 %0, t; }" : "=r"(a) : "l"(p));
    return a;
}
__device__ __forceinline__ void cp16(uint32_t saddr, const void* g) {
    asm volatile("cp.async.cg.shared.global [%0], [%1], 16;" :: "r"(saddr), "l"(g));
}
#define CP_COMMIT() asm volatile("cp.async.commit_group;" ::: "memory")
#define CP_WAIT(n)  asm volatile("cp.async.wait_group %0;" :: "n"(n) : "memory")

__device__ __forceinline__ void ldsm4(uint32_t (&r)[4], uint32_t addr) {
    asm volatile("ldmatrix.sync.aligned.m8n8.x4.shared.b16 {%0,%1,%2,%3}, [%4];"
                 : "=r"(r[0]), "=r"(r[1]), "=r"(r[2]), "=r"(r[3]) : "r"(addr));
}
__device__ __forceinline__ void mma16816(float (&d)[4], const uint32_t (&a)[4],
                                         const uint32_t* b) {
    asm volatile(
        "mma.sync.aligned.m16n8k16.row.col.f32.f16.f16.f32 "
        "{%0,%1,%2,%3}, {%4,%5,%6,%7}, {%8,%9}, {%0,%1,%2,%3};"
        : "+f"(d[0]), "+f"(d[1]), "+f"(d[2]), "+f"(d[3])
        : "r"(a[0]), "r"(a[1]), "r"(a[2]), "r"(a[3]), "r"(b[0]), "r"(b[1]));
}
#define SW128(o) ((o) ^ (((o) >> 3) & 0x70))

// ---------------- LayerNorm -> fp16 ----------------
__global__ __launch_bounds__(256) void ln_kernel(const float* __restrict__ x,
                                                 const float* __restrict__ w,
                                                 const float* __restrict__ b) {
    int row = blockIdx.x;
    int tid = threadIdx.x;
    const float4 v = ((const float4*)(x + (size_t)row * DMODEL))[tid];
    float s  = v.x + v.y + v.z + v.w;
    float sq = v.x*v.x + v.y*v.y + v.z*v.z + v.w*v.w;
    #pragma unroll
    for (int o = 16; o > 0; o >>= 1) {
        s  += __shfl_xor_sync(0xffffffffu, s, o);
        sq += __shfl_xor_sync(0xffffffffu, sq, o);
    }
    __shared__ float ss[8], sqs[8];
    if ((tid & 31) == 0) { ss[tid >> 5] = s; sqs[tid >> 5] = sq; }
    __syncthreads();
    float tot = 0.f, totq = 0.f;
    #pragma unroll
    for (int p = 0; p < 8; p++) { tot += ss[p]; totq += sqs[p]; }
    float mean = tot * (1.f / DMODEL);
    float var  = totq * (1.f / DMODEL) - mean * mean;
    float r = rsqrtf(var + 1e-5f);
    const float4 w4 = ((const float4*)w)[tid];
    const float4 b4 = ((const float4*)b)[tid];
    float o[4];
    o[0] = (v.x - mean) * r * w4.x + b4.x;
    o[1] = (v.y - mean) * r * w4.y + b4.y;
    o[2] = (v.z - mean) * r * w4.z + b4.z;
    o[3] = (v.w - mean) * r * w4.w + b4.w;
    size_t base = (size_t)row * DMODEL + tid * 4;
    *(__half2*)(g_XNh + base)     = __floats2half2_rn(o[0], o[1]);
    *(__half2*)(g_XNh + base + 2) = __floats2half2_rn(o[2], o[3]);
}

// ---------------- weight transpose: W[K][N] -> T[N][K] fp16 ----------------
__global__ __launch_bounds__(256) void wtrans_kernel(const float* __restrict__ W,
                                                     __half* __restrict__ Th,
                                                     int K, int N) {
    __shared__ float t[32][33];
    int n0 = blockIdx.x * 32, k0 = blockIdx.y * 32;
    int tx = threadIdx.x & 31, ty = threadIdx.x >> 5;   // 32 x 8
    #pragma unroll
    for (int i = 0; i < 4; i++)
        t[ty + 8 * i][tx] = W[(size_t)(k0 + ty + 8 * i) * N + n0 + tx];
    __syncthreads();
    #pragma unroll
    for (int i = 0; i < 4; i++) {
        int n = ty + 8 * i, kk = tx;
        Th[(size_t)(n0 + n) * K + k0 + kk] = __float2half(t[kk][n]);
    }
}

// ---------------- fp16 mma.sync GEMM: C[M,N] = A @ B^T ----------------
// A: Ah [M][K] fp16 ; B: Bh [N][K] fp16 (pre-transposed weights)
// MODE 0: plain  MODE 1: softplus(acc + bias[col])  MODE 2: acc + res[row*ldc+col]
// CTA tile 128x128, K-chunk 64; 2-stage cp.async pipeline; SW128 smem swizzle.
#define TILE_B   16384                // one 128x64 fp16 tile
#define STAGE_B  (2 * TILE_B)         // Ah, Bh
#define GEMM_SMEM (2 * STAGE_B)       // 65536

template <int MODE>
__global__ void __launch_bounds__(256, 2)
tgemm_kernel(const __half* __restrict__ Ah, const __half* __restrict__ Bh,
             float* __restrict__ C, int K, int ldc,
             const float* __restrict__ bias, const float* __restrict__ res) {
    extern __shared__ char smem[];
    uint32_t sb = smem_u32(smem);
    int tid = threadIdx.x, lane = tid & 31, wid = tid >> 5;
    int warp_m = wid & 1;          // 2 x 64 rows
    int warp_n = wid >> 1;         // 4 x 32 cols
    int m0 = blockIdx.y * 128, n0 = blockIdx.x * 128;

    float acc[4][4][4];
    #pragma unroll
    for (int i = 0; i < 4; i++)
        #pragma unroll
        for (int j = 0; j < 4; j++)
            #pragma unroll
            for (int q = 0; q < 4; q++) acc[i][j][q] = 0.f;

    // load mapping: thread -> (row = tid/2, half = tid&1), 4 x 16B per tile
    int lrow = tid >> 1, lhalf = tid & 1;
    const char* gAh = (const char*)(Ah + (size_t)(m0 + lrow) * K) + lhalf * 64;
    const char* gBh = (const char*)(Bh + (size_t)(n0 + lrow) * K) + lhalf * 64;
    uint32_t swo[4];
    #pragma unroll
    for (int i = 0; i < 4; i++)
        swo[i] = SW128((uint32_t)(lrow * 128 + lhalf * 64 + i * 16));

    int nc = K >> 6;

    // prefetch chunk 0 into stage 0
    {
        #pragma unroll
        for (int i = 0; i < 4; i++) {
            cp16(sb + swo[i],          gAh + i * 16);
            cp16(sb + TILE_B + swo[i], gBh + i * 16);
        }
        CP_COMMIT();
    }

    for (int c = 0; c < nc; c++) {
        if (c + 1 < nc) {
            uint32_t base = sb + ((c + 1) & 1) * STAGE_B;
            size_t kb = (size_t)(c + 1) * 128;
            #pragma unroll
            for (int i = 0; i < 4; i++) {
                cp16(base + swo[i],          gAh + kb + i * 16);
                cp16(base + TILE_B + swo[i], gBh + kb + i * 16);
            }
            CP_COMMIT();
            CP_WAIT(1);
        } else {
            CP_WAIT(0);
        }
        __syncthreads();

        uint32_t cbase = sb + (c & 1) * STAGE_B;
        #pragma unroll
        for (int ks = 0; ks < 4; ks++) {
            uint32_t af[4][4];
            uint32_t bf[2][4];
            #pragma unroll
            for (int mi = 0; mi < 4; mi++) {
                uint32_t off = SW128((uint32_t)((warp_m * 64 + mi * 16 + (lane & 15)) * 128
                                                + ks * 32 + (lane >> 4) * 16));
                ldsm4(af[mi], cbase + off);
            }
            #pragma unroll
            for (int p = 0; p < 2; p++) {
                uint32_t off = SW128((uint32_t)((warp_n * 32 + p * 16 + ((lane >> 4) & 1) * 8
                                                + (lane & 7)) * 128
                                                + ks * 32 + ((lane >> 3) & 1) * 16));
                ldsm4(bf[p], cbase + TILE_B + off);
            }
            #pragma unroll
            for (int mi = 0; mi < 4; mi++) {
                #pragma unroll
                for (int ni = 0; ni < 4; ni++) {
                    mma16816(acc[mi][ni], af[mi], &bf[ni >> 1][(ni & 1) * 2]);
                }
            }
        }
        __syncthreads();
    }

    // epilogue straight from register accumulators
    #pragma unroll
    for (int mi = 0; mi < 4; mi++) {
        int r0 = m0 + warp_m * 64 + mi * 16 + (lane >> 2);
        #pragma unroll
        for (int ni = 0; ni < 4; ni++) {
            int col = n0 + warp_n * 32 + ni * 8 + (lane & 3) * 2;
            #pragma unroll
            for (int half = 0; half < 2; half++) {
                int row = r0 + half * 8;
                float a0 = acc[mi][ni][half * 2 + 0];
                float a1 = acc[mi][ni][half * 2 + 1];
                if (MODE == 1) {
                    a0 += bias[col];
                    a1 += bias[col + 1];
                    a0 = fmaxf(a0, 0.f) + log1pf(expf(-fabsf(a0)));
                    a1 = fmaxf(a1, 0.f) + log1pf(expf(-fabsf(a1)));
                } else if (MODE == 2) {
                    const float2 rr = *(const float2*)(res + (size_t)row * ldc + col);
                    a0 += rr.x; a1 += rr.y;
                }
                float2 o; o.x = a0; o.y = a1;
                *(float2*)(C + (size_t)row * ldc + col) = o;
            }
        }
    }
}

// ---------------- depthwise causal conv (K=4) + SiLU -> fp32 + fp16 ----------------
__global__ __launch_bounds__(256) void conv_kernel(const float* __restrict__ cw,
                                                   const float* __restrict__ cb) {
    int idx = blockIdx.x * 256 + threadIdx.x;
    int d = idx & (DINNER - 1);
    int l = (idx >> 11) & (LSEQ - 1);
    int b = idx >> 22;
    float acc = cb[d];
    #pragma unroll
    for (int k = 0; k < DCONV; k++) {
        int t = l - (DCONV - 1) + k;
        if (t >= 0)
            acc = fmaf(cw[d * DCONV + k],
                       g_XZ[((size_t)(b * LSEQ + t)) * (2 * DINNER) + d], acc);
    }
    float s = acc / (1.f + __expf(-acc));
    g_XC[(size_t)idx] = s;
    g_XCh[(size_t)idx] = __float2half(s);
}

// ---------------- B/C projections: 32 rows per block, W staged via smem ----------------
__global__ __launch_bounds__(256) void bc_kernel(const float* __restrict__ Wb,
                                                 const float* __restrict__ Wc) {
    __shared__ float Xs[32][132];
    __shared__ float Ws[128][32];
    int tid = threadIdx.x;
    int out = tid & 31, rg = tid >> 5;         // 8 rowgroups x 4 rows
    int rb0 = blockIdx.x * 32;
    float acc[4] = {0.f, 0.f, 0.f, 0.f};

    for (int k0 = 0; k0 < DINNER; k0 += 128) {
        #pragma unroll
        for (int i = 0; i < 4; i++) {
            int lin = tid + i * 256;
            int rr = lin >> 5, c4 = lin & 31;
            *(float4*)(&Xs[rr][c4 * 4]) =
                *(const float4*)(g_XC + (size_t)(rb0 + rr) * DINNER + k0 + c4 * 4);
        }
        #pragma unroll
        for (int i = 0; i < 2; i++) {
            int lin = tid + i * 256;
            int kk = lin >> 2, q = lin & 3;
            *(float4*)(&Ws[kk][q * 4]) = *(const float4*)(Wb + (size_t)(k0 + kk) * DSTATE + q * 4);
        }
        #pragma unroll
        for (int i = 0; i < 2; i++) {
            int lin = tid + i * 256;
            int kk = lin >> 2, q = lin & 3;
            *(float4*)(&Ws[kk][16 + q * 4]) = *(const float4*)(Wc + (size_t)(k0 + kk) * DSTATE + q * 4);
        }
        __syncthreads();
        for (int k = 0; k < 128; k++) {
            float w = Ws[k][out];
            #pragma unroll
            for (int i = 0; i < 4; i++)
                acc[i] = fmaf(Xs[rg * 4 + i][k], w, acc[i]);
        }
        __syncthreads();
    }
    #pragma unroll
    for (int i = 0; i < 4; i++) {
        int row = rb0 + rg * 4 + i;
        if (out < DSTATE) g_BM[row * DSTATE + out] = acc[i];
        else              g_CM[row * DSTATE + (out - DSTATE)] = acc[i];
    }
}

// ---------------- selective scan + gate -> fp16 ----------------
#define SCAN_BLK 64
#define SCAN_CH 64
__global__ __launch_bounds__(SCAN_BLK) void scan_kernel(const float* __restrict__ A_log,
                                                        const float* __restrict__ Dp_) {
    int b = blockIdx.y;
    int d = blockIdx.x * SCAN_BLK + threadIdx.x;
    int tid = threadIdx.x;

    float A[DSTATE], h[DSTATE];
    #pragma unroll
    for (int n = 0; n < DSTATE; n++) {
        A[n] = -__expf(A_log[d * DSTATE + n]);
        h[n] = 0.f;
    }
    float Dp = Dp_[d];

    __shared__ float Bsh[SCAN_CH][DSTATE];
    __shared__ float Csh[SCAN_CH][DSTATE];

    for (int t0 = 0; t0 < LSEQ; t0 += SCAN_CH) {
        int base = (b * LSEQ + t0) * DSTATE;
        for (int i = tid; i < SCAN_CH * DSTATE; i += SCAN_BLK) {
            Bsh[i >> 4][i & 15] = g_BM[base + i];
            Csh[i >> 4][i & 15] = g_CM[base + i];
        }
        __syncthreads();
        for (int tt = 0; tt < SCAN_CH; tt++) {
            int t = t0 + tt;
            size_t rb = (size_t)(b * LSEQ + t) * DINNER + d;
            float dt = g_DELTA[rb];
            float xt = g_XC[rb];
            float dx = dt * xt;
            float y = 0.f;
            #pragma unroll
            for (int n = 0; n < DSTATE; n++) {
                float ab = __expf(dt * A[n]);
                h[n] = fmaf(ab, h[n], dx * Bsh[tt][n]);
                y = fmaf(h[n], Csh[tt][n], y);
            }
            y = fmaf(Dp, xt, y);
            float z = g_XZ[(size_t)(b * LSEQ + t) * (2 * DINNER) + DINNER + d];
            float sz = z / (1.f + __expf(-z));
            g_YWh[rb] = __float2half(y * sz);
        }
        __syncthreads();
    }
}

// ---------------- launch ----------------
extern "C" void kernel_launch(void* const* d_in, const int* in_sizes, int n_in,
                              void* d_out, int out_size) {
    const float* x       = (const float*)d_in[0];
    const float* norm_w  = (const float*)d_in[1];
    const float* norm_b  = (const float*)d_in[2];
    const float* W_in    = (const float*)d_in[3];
    const float* conv_w  = (const float*)d_in[4];
    const float* conv_b  = (const float*)d_in[5];
    const float* A_log   = (const float*)d_in[6];
    const float* W_b     = (const float*)d_in[7];
    const float* W_c     = (const float*)d_in[8];
    const float* W_delta = (const float*)d_in[9];
    const float* b_delta = (const float*)d_in[10];
    const float* D_param = (const float*)d_in[11];
    const float* W_out   = (const float*)d_in[12];
    float* out = (float*)d_out;

    void *pXZ, *pDELTA, *pXNh, *pXCh, *pYWh, *pWih, *pWdh, *pWoh;
    cudaGetSymbolAddress(&pXZ, g_XZ);
    cudaGetSymbolAddress(&pDELTA, g_DELTA);
    cudaGetSymbolAddress(&pXNh, g_XNh);
    cudaGetSymbolAddress(&pXCh, g_XCh);
    cudaGetSymbolAddress(&pYWh, g_YWh);
    cudaGetSymbolAddress(&pWih, g_Wih);
    cudaGetSymbolAddress(&pWdh, g_Wdh);
    cudaGetSymbolAddress(&pWoh, g_Woh);

    cudaFuncSetAttribute(tgemm_kernel<0>, cudaFuncAttributeMaxDynamicSharedMemorySize, GEMM_SMEM);
    cudaFuncSetAttribute(tgemm_kernel<1>, cudaFuncAttributeMaxDynamicSharedMemorySize, GEMM_SMEM);
    cudaFuncSetAttribute(tgemm_kernel<2>, cudaFuncAttributeMaxDynamicSharedMemorySize, GEMM_SMEM);

    // weight transpose + fp16 convert
    wtrans_kernel<<<dim3(2 * DINNER / 32, DMODEL / 32), 256>>>(
        W_in, (__half*)pWih, DMODEL, 2 * DINNER);
    wtrans_kernel<<<dim3(DINNER / 32, DINNER / 32), 256>>>(
        W_delta, (__half*)pWdh, DINNER, DINNER);
    wtrans_kernel<<<dim3(DMODEL / 32, DINNER / 32), 256>>>(
        W_out, (__half*)pWoh, DINNER, DMODEL);

    // 1) layernorm -> XN fp16
    ln_kernel<<<MROWS, 256>>>(x, norm_w, norm_b);

    // 2) xz = xn @ W_in  [8192,1024] x [1024,4096]
    tgemm_kernel<0><<<dim3(2 * DINNER / 128, MROWS / 128), 256, GEMM_SMEM>>>(
        (const __half*)pXNh, (const __half*)pWih,
        (float*)pXZ, DMODEL, 2 * DINNER, nullptr, nullptr);

    // 3) depthwise causal conv + silu -> XC fp32 + fp16
    conv_kernel<<<(B_SZ * LSEQ * DINNER) / 256, 256>>>(conv_w, conv_b);

    // 4) delta = softplus(xc @ W_delta + b_delta)  [8192,2048] x [2048,2048]
    tgemm_kernel<1><<<dim3(DINNER / 128, MROWS / 128), 256, GEMM_SMEM>>>(
        (const __half*)pXCh, (const __half*)pWdh,
        (float*)pDELTA, DINNER, DINNER, b_delta, nullptr);

    // 5) B/C projections
    bc_kernel<<<MROWS / 32, 256>>>(W_b, W_c);

    // 6) selective scan + D skip + silu(z) gate -> YW fp16
    scan_kernel<<<dim3(DINNER / SCAN_BLK, B_SZ), SCAN_BLK>>>(A_log, D_param);

    // 7) out = yw @ W_out + residual  [8192,2048] x [2048,1024]
    tgemm_kernel<2><<<dim3(DMODEL / 128, MROWS / 128), 256, GEMM_SMEM>>>(
        (const __half*)pYWh, (const __half*)pWoh,
        out, DINNER, DMODEL, nullptr, x);
}